// round 1
// baseline (speedup 1.0000x reference)
#include <cuda_runtime.h>
#include <cstdint>

// Problem constants (fixed shapes for this problem instance)
#define MAXV 50000
#define MAXE 800000
#define NODE_IN 128
#define EDGE_IN 16
#define HF 128          // HEADS*OUT
#define HEADS 4
#define OUTF 32
#define NEG_SLOPE 0.2f

// ---------------- device scratch (no allocations allowed) ----------------
__device__ float g_ft[MAXV * HF];       // projected node feats
__device__ float g_el[MAXV * HEADS];
__device__ float g_er[MAXV * HEADS];
__device__ float g_esum[MAXV * HEADS];
__device__ float g_ex[MAXE * HEADS];    // exp(logit) per edge
__device__ int   g_deg[MAXV];
__device__ int   g_incl[MAXV];
__device__ int   g_bsum[64];
__device__ int   g_boff[64];
__device__ int   g_rowptr[MAXV + 1];
__device__ int   g_cursor[MAXV];
__device__ int   g_csr[MAXE];           // edge ids grouped by dst
__device__ float g_wer[EDGE_IN * HEADS];// folded W_edge * attn_e

// ---------------- small utility kernels ----------------
__global__ void k_zero(int V) {
    int i = blockIdx.x * blockDim.x + threadIdx.x;
    if (i < V) g_deg[i] = 0;
    if (i < V * HEADS) g_esum[i] = 0.0f;
}

__global__ void k_hist(const int* __restrict__ dst, int E) {
    int i = blockIdx.x * blockDim.x + threadIdx.x;
    if (i < E) atomicAdd(&g_deg[dst[i]], 1);
}

__global__ void k_scan1(int V) {
    __shared__ int wsum[32];
    int b = blockIdx.x, t = threadIdx.x;
    int i = b * 1024 + t;
    int val = (i < V) ? g_deg[i] : 0;
    int lane = t & 31, wid = t >> 5;
    int x = val;
    #pragma unroll
    for (int o = 1; o < 32; o <<= 1) {
        int y = __shfl_up_sync(0xFFFFFFFFu, x, o);
        if (lane >= o) x += y;
    }
    if (lane == 31) wsum[wid] = x;
    __syncthreads();
    if (wid == 0) {
        int s = wsum[lane];
        #pragma unroll
        for (int o = 1; o < 32; o <<= 1) {
            int y = __shfl_up_sync(0xFFFFFFFFu, s, o);
            if (lane >= o) s += y;
        }
        wsum[lane] = s;
    }
    __syncthreads();
    int incl = x + (wid > 0 ? wsum[wid - 1] : 0);
    if (i < V) g_incl[i] = incl;
    if (t == 1023) g_bsum[b] = incl;
}

__global__ void k_scan2(int nblk) {
    if (threadIdx.x == 0 && blockIdx.x == 0) {
        int acc = 0;
        for (int b = 0; b < nblk; b++) { g_boff[b] = acc; acc += g_bsum[b]; }
    }
}

__global__ void k_scan3(int V) {
    int b = blockIdx.x;
    int i = b * 1024 + threadIdx.x;
    if (i < V) {
        int incl = g_incl[i] + g_boff[b];
        g_rowptr[i + 1] = incl;
        g_cursor[i] = incl - g_deg[i];
        if (i == 0) g_rowptr[0] = 0;
    }
}

__global__ void k_fill(const int* __restrict__ dst, int E) {
    int i = blockIdx.x * blockDim.x + threadIdx.x;
    if (i < E) {
        int pos = atomicAdd(&g_cursor[dst[i]], 1);
        g_csr[pos] = i;
    }
}

// fold W_edge with attn_e:  wer[j][h] = sum_f W_edge[j, h*32+f] * attn_e[h,f]
__global__ void k_fold(const float* __restrict__ We, const float* __restrict__ ae) {
    int t = threadIdx.x;
    if (t < EDGE_IN * HEADS) {
        int j = t >> 2, h = t & 3;
        float s = 0.0f;
        #pragma unroll
        for (int f = 0; f < OUTF; f++)
            s += We[j * HF + h * OUTF + f] * ae[h * OUTF + f];
        g_wer[j * HEADS + h] = s;
    }
}

// ---------------- node projection GEMM: ft = X@Wn, out = X@Wr + bias -----
// block: 256 threads, 32 nodes per block. Each thread: 4 rows x (4+4) cols.
__global__ void __launch_bounds__(256) k_nodeproj(
    const float* __restrict__ nf, const float* __restrict__ Wn,
    const float* __restrict__ Wr, const float* __restrict__ bias,
    float* __restrict__ out, int V)
{
    __shared__ float xs[32][NODE_IN];
    int v0 = blockIdx.x * 32;
    int tid = threadIdx.x;

    #pragma unroll
    for (int i = 0; i < 4; i++) {
        int idx = tid + i * 256;        // 0..1023
        int r = idx >> 5;               // row 0..31
        int c4 = idx & 31;              // float4 col group
        int v = v0 + r;
        float4 val = make_float4(0.f, 0.f, 0.f, 0.f);
        if (v < V) val = *reinterpret_cast<const float4*>(nf + (size_t)v * NODE_IN + c4 * 4);
        *reinterpret_cast<float4*>(&xs[r][c4 * 4]) = val;
    }
    __syncthreads();

    int cg = tid & 31;   // col group: cols cg*4 .. cg*4+3
    int rg = tid >> 5;   // row group: rows rg*4 .. rg*4+3

    float an[4][4], ar[4][4];
    #pragma unroll
    for (int i = 0; i < 4; i++)
        #pragma unroll
        for (int j = 0; j < 4; j++) { an[i][j] = 0.f; ar[i][j] = 0.f; }

    #pragma unroll 8
    for (int k4 = 0; k4 < NODE_IN / 4; k4++) {
        float4 xr[4];
        #pragma unroll
        for (int i = 0; i < 4; i++)
            xr[i] = *reinterpret_cast<const float4*>(&xs[rg * 4 + i][k4 * 4]);
        #pragma unroll
        for (int kk = 0; kk < 4; kk++) {
            int k = k4 * 4 + kk;
            float4 wn = __ldg(reinterpret_cast<const float4*>(Wn + (size_t)k * HF + cg * 4));
            float4 wr = __ldg(reinterpret_cast<const float4*>(Wr + (size_t)k * HF + cg * 4));
            #pragma unroll
            for (int i = 0; i < 4; i++) {
                float x = (kk == 0) ? xr[i].x : (kk == 1) ? xr[i].y : (kk == 2) ? xr[i].z : xr[i].w;
                an[i][0] += x * wn.x; an[i][1] += x * wn.y; an[i][2] += x * wn.z; an[i][3] += x * wn.w;
                ar[i][0] += x * wr.x; ar[i][1] += x * wr.y; ar[i][2] += x * wr.z; ar[i][3] += x * wr.w;
            }
        }
    }

    float4 b4 = *reinterpret_cast<const float4*>(bias + cg * 4);
    #pragma unroll
    for (int i = 0; i < 4; i++) {
        int v = v0 + rg * 4 + i;
        if (v < V) {
            float4 f = make_float4(an[i][0], an[i][1], an[i][2], an[i][3]);
            float4 r = make_float4(ar[i][0] + b4.x, ar[i][1] + b4.y, ar[i][2] + b4.z, ar[i][3] + b4.w);
            *reinterpret_cast<float4*>(g_ft + (size_t)v * HF + cg * 4) = f;
            *reinterpret_cast<float4*>(out + (size_t)v * HF + cg * 4) = r;
        }
    }
}

// ---------------- per-node attention projections el, er ----------------
__global__ void k_elr(const float* __restrict__ al, const float* __restrict__ ar, int V) {
    int gw = (blockIdx.x * blockDim.x + threadIdx.x) >> 5;  // warp = node
    int lane = threadIdx.x & 31;
    if (gw >= V) return;
    #pragma unroll
    for (int h = 0; h < HEADS; h++) {
        float x = g_ft[(size_t)gw * HF + h * OUTF + lane];
        float pl = x * __ldg(al + h * OUTF + lane);
        float pr = x * __ldg(ar + h * OUTF + lane);
        #pragma unroll
        for (int o = 16; o > 0; o >>= 1) {
            pl += __shfl_xor_sync(0xFFFFFFFFu, pl, o);
            pr += __shfl_xor_sync(0xFFFFFFFFu, pr, o);
        }
        if (lane == 0) { g_el[gw * HEADS + h] = pl; g_er[gw * HEADS + h] = pr; }
    }
}

// ---------------- edge logits + exp + segment-sum denominator ----------
__global__ void k_edge(const float* __restrict__ ef, const int* __restrict__ src,
                       const int* __restrict__ dst, int E)
{
    __shared__ float swer[EDGE_IN * HEADS];
    if (threadIdx.x < EDGE_IN * HEADS) swer[threadIdx.x] = g_wer[threadIdx.x];
    __syncthreads();

    int i = blockIdx.x * blockDim.x + threadIdx.x;
    if (i >= E) return;

    float efv[16];
    #pragma unroll
    for (int q = 0; q < 4; q++) {
        float4 e4 = __ldg(reinterpret_cast<const float4*>(ef + (size_t)i * EDGE_IN + q * 4));
        efv[q * 4 + 0] = e4.x; efv[q * 4 + 1] = e4.y; efv[q * 4 + 2] = e4.z; efv[q * 4 + 3] = e4.w;
    }
    float ee0 = 0.f, ee1 = 0.f, ee2 = 0.f, ee3 = 0.f;
    #pragma unroll
    for (int j = 0; j < EDGE_IN; j++) {
        float e = efv[j];
        ee0 += e * swer[j * 4 + 0];
        ee1 += e * swer[j * 4 + 1];
        ee2 += e * swer[j * 4 + 2];
        ee3 += e * swer[j * 4 + 3];
    }

    int s = src[i], d = dst[i];
    float4 el4 = *reinterpret_cast<const float4*>(&g_el[s * HEADS]);
    float4 er4 = *reinterpret_cast<const float4*>(&g_er[d * HEADS]);

    float t0 = el4.x + er4.x + ee0;
    float t1 = el4.y + er4.y + ee1;
    float t2 = el4.z + er4.z + ee2;
    float t3 = el4.w + er4.w + ee3;
    t0 = (t0 >= 0.f) ? t0 : NEG_SLOPE * t0;
    t1 = (t1 >= 0.f) ? t1 : NEG_SLOPE * t1;
    t2 = (t2 >= 0.f) ? t2 : NEG_SLOPE * t2;
    t3 = (t3 >= 0.f) ? t3 : NEG_SLOPE * t3;
    // softmax is shift-invariant; logits are O(1) -> no max pass needed
    float x0 = __expf(t0), x1 = __expf(t1), x2 = __expf(t2), x3 = __expf(t3);

    *reinterpret_cast<float4*>(&g_ex[(size_t)i * HEADS]) = make_float4(x0, x1, x2, x3);

    float* ep = &g_esum[d * HEADS];
    asm volatile("red.global.add.v4.f32 [%0], {%1,%2,%3,%4};"
                 :: "l"(ep), "f"(x0), "f"(x1), "f"(x2), "f"(x3) : "memory");
}

// ---------------- per-dst aggregation (CSR, one block per node) ---------
__global__ void __launch_bounds__(128) k_agg(const int* __restrict__ src,
                                             float* __restrict__ out, int V)
{
    __shared__ int   s_src[128];
    __shared__ float s_a[HEADS][128];

    int v = blockIdx.x;
    int t = threadIdx.x;
    int beg = g_rowptr[v], end = g_rowptr[v + 1];
    if (end <= beg) return;  // residual+bias already in out

    int h = t >> 5;
    float4 es = *reinterpret_cast<const float4*>(&g_esum[v * HEADS]);
    float iv0 = 1.0f / es.x, iv1 = 1.0f / es.y, iv2 = 1.0f / es.z, iv3 = 1.0f / es.w;

    float acc = out[(size_t)v * HF + t];

    for (int pos = beg; pos < end; pos += 128) {
        int cnt = min(128, end - pos);
        __syncthreads();
        if (t < cnt) {
            int eid = g_csr[pos + t];
            s_src[t] = src[eid];
            float4 ex = *reinterpret_cast<const float4*>(&g_ex[(size_t)eid * HEADS]);
            s_a[0][t] = ex.x * iv0;
            s_a[1][t] = ex.y * iv1;
            s_a[2][t] = ex.z * iv2;
            s_a[3][t] = ex.w * iv3;
        }
        __syncthreads();
        #pragma unroll 4
        for (int j = 0; j < cnt; j++) {
            acc += s_a[h][j] * __ldg(g_ft + (size_t)s_src[j] * HF + t);
        }
    }
    out[(size_t)v * HF + t] = acc;
}

// ---------------- launch ----------------
extern "C" void kernel_launch(void* const* d_in, const int* in_sizes, int n_in,
                              void* d_out, int out_size)
{
    const float* nf   = (const float*)d_in[0];
    const float* ef   = (const float*)d_in[1];
    const int*   src  = (const int*)d_in[2];
    const int*   dst  = (const int*)d_in[3];
    const float* Wn   = (const float*)d_in[4];
    const float* We   = (const float*)d_in[5];
    const float* al   = (const float*)d_in[6];
    const float* ar   = (const float*)d_in[7];
    const float* ae   = (const float*)d_in[8];
    const float* Wr   = (const float*)d_in[9];
    const float* bias = (const float*)d_in[10];
    float* out = (float*)d_out;

    int V = in_sizes[0] / NODE_IN;
    int E = in_sizes[2];
    if (V > MAXV) V = MAXV;
    if (E > MAXE) E = MAXE;

    int nch = (V + 1023) / 1024;

    k_zero<<<(V * HEADS + 255) / 256, 256>>>(V);
    k_hist<<<(E + 255) / 256, 256>>>(dst, E);
    k_scan1<<<nch, 1024>>>(V);
    k_scan2<<<1, 32>>>(nch);
    k_scan3<<<nch, 1024>>>(V);
    k_fill<<<(E + 255) / 256, 256>>>(dst, E);

    k_fold<<<1, 64>>>(We, ae);
    k_nodeproj<<<(V + 31) / 32, 256>>>(nf, Wn, Wr, bias, out, V);
    k_elr<<<(V * 32 + 255) / 256, 256>>>(al, ar, V);
    k_edge<<<(E + 127) / 128, 128>>>(ef, src, dst, E);
    k_agg<<<V, 128>>>(src, out, V);
}

// round 2
// speedup vs baseline: 1.0773x; 1.0773x over previous
#include <cuda_runtime.h>
#include <cstdint>

#define MAXV 50000
#define MAXE 800000
#define NODE_IN 128
#define EDGE_IN 16
#define HF 128
#define HEADS 4
#define OUTF 32
#define NEG_SLOPE 0.2f
#define ETILE 64

// ---------------- device scratch ----------------
__device__ float g_ft[MAXV * HF];
__device__ float g_el[MAXV * HEADS];
__device__ float g_er[MAXV * HEADS];
__device__ float g_esum[MAXV * HEADS];
__device__ float g_ex[MAXE * HEADS];
__device__ int   g_deg[MAXV];
__device__ int   g_incl[MAXV];
__device__ int   g_bsum[64];
__device__ int   g_rowptr[MAXV + 1];
__device__ int   g_cursor[MAXV];
__device__ int   g_csr[MAXE];
__device__ float g_wer[EDGE_IN * HEADS];

// ---------------- f32x2 helpers ----------------
__device__ __forceinline__ unsigned long long pack2(float x) {
    unsigned long long r;
    asm("mov.b64 %0, {%1, %1};" : "=l"(r) : "f"(x));
    return r;
}
__device__ __forceinline__ void fma2(unsigned long long& d, unsigned long long a, unsigned long long b) {
    asm("fma.rn.f32x2 %0, %1, %2, %0;" : "+l"(d) : "l"(a), "l"(b));
}
__device__ __forceinline__ float2 unpack2(unsigned long long v) {
    float2 f;
    asm("mov.b64 {%0, %1}, %2;" : "=f"(f.x), "=f"(f.y) : "l"(v));
    return f;
}

// ---------------- CSR-build kernels (stream A) ----------------
__global__ void k_zero(int V) {
    int i = blockIdx.x * blockDim.x + threadIdx.x;
    if (i < V) g_deg[i] = 0;
}

__global__ void k_hist(const int* __restrict__ dst, int E) {
    int i = blockIdx.x * blockDim.x + threadIdx.x;
    if (i < E) atomicAdd(&g_deg[dst[i]], 1);
}

__global__ void k_scan1(int V) {
    __shared__ int wsum[32];
    int b = blockIdx.x, t = threadIdx.x;
    int i = b * 1024 + t;
    int val = (i < V) ? g_deg[i] : 0;
    int lane = t & 31, wid = t >> 5;
    int x = val;
    #pragma unroll
    for (int o = 1; o < 32; o <<= 1) {
        int y = __shfl_up_sync(0xFFFFFFFFu, x, o);
        if (lane >= o) x += y;
    }
    if (lane == 31) wsum[wid] = x;
    __syncthreads();
    if (wid == 0) {
        int s = wsum[lane];
        #pragma unroll
        for (int o = 1; o < 32; o <<= 1) {
            int y = __shfl_up_sync(0xFFFFFFFFu, s, o);
            if (lane >= o) s += y;
        }
        wsum[lane] = s;
    }
    __syncthreads();
    int incl = x + (wid > 0 ? wsum[wid - 1] : 0);
    if (i < V) g_incl[i] = incl;
    if (t == 1023) g_bsum[b] = incl;
}

// merged scan2+scan3: each block computes its own prefix of block sums
__global__ void k_scan3(int V) {
    __shared__ int soff;
    int b = blockIdx.x, t = threadIdx.x;
    if (t < 32) {
        int s = 0;
        for (int j = t; j < b; j += 32) s += g_bsum[j];
        #pragma unroll
        for (int o = 16; o > 0; o >>= 1) s += __shfl_xor_sync(0xFFFFFFFFu, s, o);
        if (t == 0) soff = s;
    }
    __syncthreads();
    int i = b * 1024 + t;
    if (i < V) {
        int incl = g_incl[i] + soff;
        g_rowptr[i + 1] = incl;
        g_cursor[i] = incl - g_deg[i];
        if (i == 0) g_rowptr[0] = 0;
    }
}

__global__ void k_fill(const int* __restrict__ dst, int E) {
    int i = blockIdx.x * blockDim.x + threadIdx.x;
    if (i < E) {
        int pos = atomicAdd(&g_cursor[dst[i]], 1);
        g_csr[pos] = i;
    }
}

// ---------------- stream B kernels ----------------
__global__ void k_fold(const float* __restrict__ We, const float* __restrict__ ae) {
    int t = threadIdx.x;
    if (t < EDGE_IN * HEADS) {
        int j = t >> 2, h = t & 3;
        float s = 0.0f;
        #pragma unroll
        for (int f = 0; f < OUTF; f++)
            s += We[j * HF + h * OUTF + f] * ae[h * OUTF + f];
        g_wer[j * HEADS + h] = s;
    }
}

__global__ void k_zesum(int n) {
    int i = blockIdx.x * blockDim.x + threadIdx.x;
    if (i < n) g_esum[i] = 0.0f;
}

// node projection: ft = X@Wn, out = X@Wr + bias, plus fused el/er reductions.
// 64 rows per block, 256 threads; thread = (rg warp 0..7 -> 8 rows, cg lane 0..31 -> 4 cols)
// f32x2 packed FMA accumulators.
__global__ void __launch_bounds__(256) k_nodeproj(
    const float* __restrict__ nf, const float* __restrict__ Wn,
    const float* __restrict__ Wr, const float* __restrict__ bias,
    const float* __restrict__ al, const float* __restrict__ ar,
    float* __restrict__ out, int V)
{
    __shared__ float xs[64][NODE_IN];
    int v0 = blockIdx.x * 64;
    int tid = threadIdx.x;

    #pragma unroll
    for (int i = 0; i < 8; i++) {
        int idx = tid + i * 256;          // 0..2047
        int r = idx >> 5;                 // row 0..63
        int c4 = idx & 31;
        int v = v0 + r;
        float4 val = make_float4(0.f, 0.f, 0.f, 0.f);
        if (v < V) val = *reinterpret_cast<const float4*>(nf + (size_t)v * NODE_IN + c4 * 4);
        *reinterpret_cast<float4*>(&xs[r][c4 * 4]) = val;
    }
    __syncthreads();

    int cg = tid & 31;
    int rg = tid >> 5;

    unsigned long long an[8][2], arr[8][2];
    #pragma unroll
    for (int i = 0; i < 8; i++) {
        an[i][0] = an[i][1] = 0ull;
        arr[i][0] = arr[i][1] = 0ull;
    }

    #pragma unroll 2
    for (int k4 = 0; k4 < NODE_IN / 4; k4++) {
        float4 xr[8];
        #pragma unroll
        for (int i = 0; i < 8; i++)
            xr[i] = *reinterpret_cast<const float4*>(&xs[rg * 8 + i][k4 * 4]);
        #pragma unroll
        for (int kk = 0; kk < 4; kk++) {
            int k = k4 * 4 + kk;
            ulonglong2 wn = *reinterpret_cast<const ulonglong2*>(Wn + (size_t)k * HF + cg * 4);
            ulonglong2 wr = *reinterpret_cast<const ulonglong2*>(Wr + (size_t)k * HF + cg * 4);
            #pragma unroll
            for (int i = 0; i < 8; i++) {
                float x = (kk == 0) ? xr[i].x : (kk == 1) ? xr[i].y : (kk == 2) ? xr[i].z : xr[i].w;
                unsigned long long xb = pack2(x);
                fma2(an[i][0], xb, wn.x);
                fma2(an[i][1], xb, wn.y);
                fma2(arr[i][0], xb, wr.x);
                fma2(arr[i][1], xb, wr.y);
            }
        }
    }

    float4 b4 = *reinterpret_cast<const float4*>(bias + cg * 4);
    int h = cg >> 3;
    const float4 alv = __ldg(reinterpret_cast<const float4*>(al + h * OUTF + (cg & 7) * 4));
    const float4 arv = __ldg(reinterpret_cast<const float4*>(ar + h * OUTF + (cg & 7) * 4));

    #pragma unroll
    for (int i = 0; i < 8; i++) {
        int v = v0 + rg * 8 + i;
        float2 n0 = unpack2(an[i][0]), n1 = unpack2(an[i][1]);
        float2 r0 = unpack2(arr[i][0]), r1 = unpack2(arr[i][1]);
        float4 fv = make_float4(n0.x, n0.y, n1.x, n1.y);
        float4 rv = make_float4(r0.x + b4.x, r0.y + b4.y, r1.x + b4.z, r1.y + b4.w);
        if (v < V) {
            *reinterpret_cast<float4*>(g_ft + (size_t)v * HF + cg * 4) = fv;
            *reinterpret_cast<float4*>(out + (size_t)v * HF + cg * 4) = rv;
        }
        // fused el/er: segmented reduce over 8-lane head groups
        float pl = fv.x * alv.x + fv.y * alv.y + fv.z * alv.z + fv.w * alv.w;
        float pr = fv.x * arv.x + fv.y * arv.y + fv.z * arv.z + fv.w * arv.w;
        pl += __shfl_xor_sync(0xFFFFFFFFu, pl, 1);
        pl += __shfl_xor_sync(0xFFFFFFFFu, pl, 2);
        pl += __shfl_xor_sync(0xFFFFFFFFu, pl, 4);
        pr += __shfl_xor_sync(0xFFFFFFFFu, pr, 1);
        pr += __shfl_xor_sync(0xFFFFFFFFu, pr, 2);
        pr += __shfl_xor_sync(0xFFFFFFFFu, pr, 4);
        if ((cg & 7) == 0 && v < V) {
            g_el[v * HEADS + h] = pl;
            g_er[v * HEADS + h] = pr;
        }
    }
}

__global__ void k_edge(const float* __restrict__ ef, const int* __restrict__ src,
                       const int* __restrict__ dst, int E)
{
    __shared__ float swer[EDGE_IN * HEADS];
    if (threadIdx.x < EDGE_IN * HEADS) swer[threadIdx.x] = g_wer[threadIdx.x];
    __syncthreads();

    int i = blockIdx.x * blockDim.x + threadIdx.x;
    if (i >= E) return;

    float efv[16];
    #pragma unroll
    for (int q = 0; q < 4; q++) {
        float4 e4 = __ldg(reinterpret_cast<const float4*>(ef + (size_t)i * EDGE_IN + q * 4));
        efv[q * 4 + 0] = e4.x; efv[q * 4 + 1] = e4.y; efv[q * 4 + 2] = e4.z; efv[q * 4 + 3] = e4.w;
    }
    float ee0 = 0.f, ee1 = 0.f, ee2 = 0.f, ee3 = 0.f;
    #pragma unroll
    for (int j = 0; j < EDGE_IN; j++) {
        float e = efv[j];
        ee0 += e * swer[j * 4 + 0];
        ee1 += e * swer[j * 4 + 1];
        ee2 += e * swer[j * 4 + 2];
        ee3 += e * swer[j * 4 + 3];
    }

    int s = src[i], d = dst[i];
    float4 el4 = *reinterpret_cast<const float4*>(&g_el[s * HEADS]);
    float4 er4 = *reinterpret_cast<const float4*>(&g_er[d * HEADS]);

    float t0 = el4.x + er4.x + ee0;
    float t1 = el4.y + er4.y + ee1;
    float t2 = el4.z + er4.z + ee2;
    float t3 = el4.w + er4.w + ee3;
    t0 = (t0 >= 0.f) ? t0 : NEG_SLOPE * t0;
    t1 = (t1 >= 0.f) ? t1 : NEG_SLOPE * t1;
    t2 = (t2 >= 0.f) ? t2 : NEG_SLOPE * t2;
    t3 = (t3 >= 0.f) ? t3 : NEG_SLOPE * t3;
    float x0 = __expf(t0), x1 = __expf(t1), x2 = __expf(t2), x3 = __expf(t3);

    *reinterpret_cast<float4*>(&g_ex[(size_t)i * HEADS]) = make_float4(x0, x1, x2, x3);

    float* ep = &g_esum[d * HEADS];
    asm volatile("red.global.add.v4.f32 [%0], {%1,%2,%3,%4};"
                 :: "l"(ep), "f"(x0), "f"(x1), "f"(x2), "f"(x3) : "memory");
}

// ---------------- aggregation: one block per dst, warp-per-edge float4 ----
__global__ void __launch_bounds__(128) k_agg(const int* __restrict__ src,
                                             float* __restrict__ out, int V)
{
    __shared__ int   s_src[ETILE];
    __shared__ float s_a[HEADS][ETILE];
    __shared__ float4 s_red[3][32];

    int v = blockIdx.x;
    int t = threadIdx.x, w = t >> 5, lane = t & 31;
    int beg = g_rowptr[v], end = g_rowptr[v + 1];
    if (end <= beg) return;

    float4 es = *reinterpret_cast<const float4*>(&g_esum[v * HEADS]);
    float iv0 = 1.0f / es.x, iv1 = 1.0f / es.y, iv2 = 1.0f / es.z, iv3 = 1.0f / es.w;

    int h = lane >> 3;
    float4 acc = make_float4(0.f, 0.f, 0.f, 0.f);

    for (int pos = beg; pos < end; pos += ETILE) {
        int cnt = min(ETILE, end - pos);
        __syncthreads();
        if (t < cnt) {
            int eid = g_csr[pos + t];
            s_src[t] = src[eid];
            float4 ex = *reinterpret_cast<const float4*>(&g_ex[(size_t)eid * HEADS]);
            s_a[0][t] = ex.x * iv0;
            s_a[1][t] = ex.y * iv1;
            s_a[2][t] = ex.z * iv2;
            s_a[3][t] = ex.w * iv3;
        }
        __syncthreads();
        #pragma unroll 2
        for (int j = w; j < cnt; j += 4) {
            int sv = s_src[j];
            float a = s_a[h][j];
            float4 f = __ldg(reinterpret_cast<const float4*>(g_ft + (size_t)sv * HF + lane * 4));
            acc.x += a * f.x; acc.y += a * f.y; acc.z += a * f.z; acc.w += a * f.w;
        }
    }

    if (w > 0) s_red[w - 1][lane] = acc;
    __syncthreads();
    if (w == 0) {
        acc.x += s_red[0][lane].x + s_red[1][lane].x + s_red[2][lane].x;
        acc.y += s_red[0][lane].y + s_red[1][lane].y + s_red[2][lane].y;
        acc.z += s_red[0][lane].z + s_red[1][lane].z + s_red[2][lane].z;
        acc.w += s_red[0][lane].w + s_red[1][lane].w + s_red[2][lane].w;
        float4* op = reinterpret_cast<float4*>(out + (size_t)v * HF + lane * 4);
        float4 o = *op;
        o.x += acc.x; o.y += acc.y; o.z += acc.z; o.w += acc.w;
        *op = o;
    }
}

// ---------------- launch with forked capture streams ----------------
static cudaStream_t g_s2 = nullptr;
static cudaEvent_t g_evFork = nullptr, g_evJoin = nullptr;

extern "C" void kernel_launch(void* const* d_in, const int* in_sizes, int n_in,
                              void* d_out, int out_size)
{
    const float* nf   = (const float*)d_in[0];
    const float* ef   = (const float*)d_in[1];
    const int*   src  = (const int*)d_in[2];
    const int*   dst  = (const int*)d_in[3];
    const float* Wn   = (const float*)d_in[4];
    const float* We   = (const float*)d_in[5];
    const float* al   = (const float*)d_in[6];
    const float* ar   = (const float*)d_in[7];
    const float* ae   = (const float*)d_in[8];
    const float* Wr   = (const float*)d_in[9];
    const float* bias = (const float*)d_in[10];
    float* out = (float*)d_out;

    int V = in_sizes[0] / NODE_IN;
    int E = in_sizes[2];
    if (V > MAXV) V = MAXV;
    if (E > MAXE) E = MAXE;

    if (!g_s2) {
        cudaStreamCreateWithFlags(&g_s2, cudaStreamNonBlocking);
        cudaEventCreateWithFlags(&g_evFork, cudaEventDisableTiming);
        cudaEventCreateWithFlags(&g_evJoin, cudaEventDisableTiming);
    }

    int nch = (V + 1023) / 1024;

    // fork: CSR build on side stream
    cudaEventRecord(g_evFork, 0);
    cudaStreamWaitEvent(g_s2, g_evFork, 0);
    k_zero<<<(V + 255) / 256, 256, 0, g_s2>>>(V);
    k_hist<<<(E + 255) / 256, 256, 0, g_s2>>>(dst, E);
    k_scan1<<<nch, 1024, 0, g_s2>>>(V);
    k_scan3<<<nch, 1024, 0, g_s2>>>(V);
    k_fill<<<(E + 255) / 256, 256, 0, g_s2>>>(dst, E);
    cudaEventRecord(g_evJoin, g_s2);

    // main chain
    k_fold<<<1, 64>>>(We, ae);
    k_zesum<<<(V * HEADS + 255) / 256, 256>>>(V * HEADS);
    k_nodeproj<<<(V + 63) / 64, 256>>>(nf, Wn, Wr, bias, al, ar, out, V);
    k_edge<<<(E + 127) / 128, 128>>>(ef, src, dst, E);

    // join, then aggregate
    cudaStreamWaitEvent(0, g_evJoin, 0);
    k_agg<<<V, 128>>>(src, out, V);
}